// round 1
// baseline (speedup 1.0000x reference)
#include <cuda_runtime.h>
#include <cstdint>

#define SEQN 65536
#define HN   128
#define G4   512   // 4*H

// Scratch (device globals: allocation-free per harness rules)
__device__ float g_GA[(size_t)SEQN * G4];   // precomputed x@WA1^T + bA1 + bA2  (128 MB)
__device__ float g_HB[(size_t)SEQN * HN];   // hB per step, consumed by fc GEMM (32 MB)

// ---------------------------------------------------------------------------
// math helpers
// ---------------------------------------------------------------------------
__device__ __forceinline__ float sigm(float x) {
    // 1/(1+e^-x); __expf overflow -> inf -> rcp -> 0, so saturates correctly
    return __fdividef(1.f, 1.f + __expf(-x));
}
__device__ __forceinline__ float tanh_(float x) {
    return 2.f * sigm(2.f * x) - 1.f;   // saturates correctly for |x| large
}

__device__ __forceinline__ void st_remote_f32(float* p, int rank, float v) {
    uint32_t addr = (uint32_t)__cvta_generic_to_shared(p);
    uint32_t raddr;
    asm volatile("mapa.shared::cluster.u32 %0, %1, %2;" : "=r"(raddr) : "r"(addr), "r"(rank));
    asm volatile("st.shared::cluster.f32 [%0], %1;" :: "r"(raddr), "f"(v) : "memory");
}

#define CLUSTER_SYNC_()                                                        \
    do {                                                                       \
        asm volatile("barrier.cluster.arrive.aligned;" ::: "memory");          \
        asm volatile("barrier.cluster.wait.aligned;" ::: "memory");            \
    } while (0)

// ---------------------------------------------------------------------------
// Kernel 1: GA[t, 512] = x[t] @ WA1^T + bA1 + bA2
// block = 128 threads; each thread holds one weight row (128 fp32) in regs.
// grid = (SEQN/64, 4): blockIdx.y selects the 128-row chunk, blockIdx.x the
// 64-timestep chunk staged in SMEM.
// ---------------------------------------------------------------------------
__global__ void __launch_bounds__(128) ga_kernel(const float* __restrict__ x,
                                                 const float* __restrict__ W,
                                                 const float* __restrict__ b1,
                                                 const float* __restrict__ b2) {
    __shared__ float xs[64 * 128];
    const int tid = threadIdx.x;
    const int row = (blockIdx.y << 7) + tid;

    float4 w[32];
    const float4* wg = (const float4*)(W + (size_t)row * 128);
#pragma unroll
    for (int k = 0; k < 32; k++) w[k] = wg[k];
    const float bias = b1[row] + b2[row];

    const int t0 = blockIdx.x * 64;
    const float4* xg = (const float4*)(x + (size_t)t0 * 128);
    float4* xs4 = (float4*)xs;
#pragma unroll
    for (int i = 0; i < 16; i++) xs4[tid + (i << 7)] = xg[tid + (i << 7)];
    __syncthreads();

    for (int tt = 0; tt < 64; tt++) {
        const float4* hx = (const float4*)(xs + tt * 128);
        float a0 = 0.f, a1 = 0.f, a2 = 0.f, a3 = 0.f;
#pragma unroll
        for (int k = 0; k < 32; k++) {
            float4 h = hx[k];
            a0 = fmaf(w[k].x, h.x, a0);
            a1 = fmaf(w[k].y, h.y, a1);
            a2 = fmaf(w[k].z, h.z, a2);
            a3 = fmaf(w[k].w, h.w, a3);
        }
        g_GA[(size_t)(t0 + tt) * G4 + row] = (a0 + a1) + (a2 + a3) + bias;
    }
}

// ---------------------------------------------------------------------------
// Kernel 2: the recurrence. 8-CTA cluster, 256 threads each.
// CTA c owns hidden indices j in [16c, 16c+16).
// Phase-1 rows per CTA: 64 WA2 rows + 64 WB2 rows (gate g, j in Jc),
// each row split into two 64-col halves -> 256 thread slots.
// Phase-2 rows per CTA: 64 WB1 rows -> 128 thread slots (tid < 128).
// h vectors replicated per-CTA in SMEM, double-buffered; updated via DSMEM
// stores + cluster.sync (x2 per step).
// ---------------------------------------------------------------------------
__global__ void __cluster_dims__(8, 1, 1) __launch_bounds__(256, 1)
recur_kernel(const float* __restrict__ WA2, const float* __restrict__ WB1,
             const float* __restrict__ WB2, const float* __restrict__ bB1,
             const float* __restrict__ bB2, const float* __restrict__ hA0,
             const float* __restrict__ cA0, const float* __restrict__ hB0,
             const float* __restrict__ cB0, float* __restrict__ out,
             int write_states) {
    __shared__ float s_hA[2][HN];
    __shared__ float s_hB[2][HN];
    __shared__ float s_uA[64];   // phase1 WA2 dots (+GA)
    __shared__ float s_vB[64];   // phase1 WB2 dots
    __shared__ float s_wB[64];   // phase2 WB1 dots
    __shared__ float s_bb[64];   // bB1+bB2 for this CTA's gate rows

    const int c   = blockIdx.x;
    const int tid = threadIdx.x;
    const int rs  = tid >> 1;     // phase1 row slot 0..127
    const int half = tid & 1;     // column half

    // ---- phase1 weights (64 fp32 each) ----
    const int r1    = (rs < 64) ? rs : rs - 64;                       // 0..63
    const int grow1 = ((r1 >> 4) << 7) + (c << 4) + (r1 & 15);        // gate*128 + j
    const float* W1p = (rs < 64) ? WA2 : WB2;
    float4 w1[16];
    {
        const float4* wg = (const float4*)(W1p + (size_t)grow1 * 128 + half * 64);
#pragma unroll
        for (int k = 0; k < 16; k++) w1[k] = wg[k];
    }

    // ---- phase2 weights (tid < 128) ----
    float4 w2[16];
    if (tid < 128) {
        const int r2    = tid >> 1;
        const int grow2 = ((r2 >> 4) << 7) + (c << 4) + (r2 & 15);
        const float4* wg = (const float4*)(WB1 + (size_t)grow2 * 128 + half * 64);
#pragma unroll
        for (int k = 0; k < 16; k++) w2[k] = wg[k];
    }

    // ---- init SMEM ----
    if (tid < 64) {
        const int grow = ((tid >> 4) << 7) + (c << 4) + (tid & 15);
        s_bb[tid] = bB1[grow] + bB2[grow];
    }
    if (tid < HN) {
        s_hA[0][tid] = hA0[tid];
        s_hB[0][tid] = hB0[tid];
    }
    float cAr = 0.f, cBr = 0.f;
    if (tid < 16) {
        cAr = cA0[(c << 4) + tid];
        cBr = cB0[(c << 4) + tid];
    }
    __syncthreads();

    // ---- GA prefetch state (one lane per WA2 row) ----
    const bool is_ga = (rs < 64) && (half == 0);
    float ga_cur = 0.f, ga_next = 0.f;
    if (is_ga) ga_cur = g_GA[grow1];

    const size_t OH = (size_t)SEQN * HN;   // state offset in d_out
    int p = 0;

    for (int t = 0; t < SEQN; t++) {
        if (is_ga)
            ga_next = (t + 1 < SEQN) ? __ldg(&g_GA[(size_t)(t + 1) * G4 + grow1]) : 0.f;

        // ===== phase 1: u = hA@WA2^T rows, v = hB@WB2^T rows =====
        {
            const float* hsrc = (rs < 64) ? s_hA[p] : s_hB[p];
            const float4* hv4 = (const float4*)(hsrc + half * 64);
            float a0 = 0.f, a1 = 0.f, a2 = 0.f, a3 = 0.f;
#pragma unroll
            for (int k = 0; k < 16; k++) {
                float4 h = hv4[k];
                a0 = fmaf(w1[k].x, h.x, a0);
                a1 = fmaf(w1[k].y, h.y, a1);
                a2 = fmaf(w1[k].z, h.z, a2);
                a3 = fmaf(w1[k].w, h.w, a3);
            }
            float s = (a0 + a1) + (a2 + a3);
            s += __shfl_down_sync(0xffffffffu, s, 1);
            if (half == 0) {
                if (rs < 64) s_uA[r1] = s + ga_cur;
                else         s_vB[r1] = s;
            }
        }
        __syncthreads();

        // ===== cell A activation + hA broadcast =====
        if (tid < 16) {
            const float gi = s_uA[tid];
            const float gf = s_uA[16 + tid];
            const float gg = s_uA[32 + tid];
            const float go = s_uA[48 + tid];
            const float cn = sigm(gf) * cAr + sigm(gi) * tanh_(gg);
            cAr = cn;
            const float h = sigm(go) * tanh_(cn);
            const int j = (c << 4) + tid;
#pragma unroll
            for (int rk = 0; rk < 8; rk++) st_remote_f32(&s_hA[p ^ 1][j], rk, h);
            if (write_states && t == SEQN - 1) {
                out[OH + j]      = h;
                out[OH + HN + j] = cn;
            }
        }
        CLUSTER_SYNC_();

        // ===== phase 2: w = hA_new@WB1^T rows =====
        if (tid < 128) {
            const float4* hv4 = (const float4*)(s_hA[p ^ 1] + half * 64);
            float a0 = 0.f, a1 = 0.f, a2 = 0.f, a3 = 0.f;
#pragma unroll
            for (int k = 0; k < 16; k++) {
                float4 h = hv4[k];
                a0 = fmaf(w2[k].x, h.x, a0);
                a1 = fmaf(w2[k].y, h.y, a1);
                a2 = fmaf(w2[k].z, h.z, a2);
                a3 = fmaf(w2[k].w, h.w, a3);
            }
            float s = (a0 + a1) + (a2 + a3);
            s += __shfl_down_sync(0xffffffffu, s, 1);
            if (half == 0) s_wB[tid >> 1] = s;
        }
        __syncthreads();

        // ===== cell B activation + hB broadcast + output =====
        if (tid < 16) {
            const float gi = s_wB[tid]      + s_vB[tid]      + s_bb[tid];
            const float gf = s_wB[16 + tid] + s_vB[16 + tid] + s_bb[16 + tid];
            const float gg = s_wB[32 + tid] + s_vB[32 + tid] + s_bb[32 + tid];
            const float go = s_wB[48 + tid] + s_vB[48 + tid] + s_bb[48 + tid];
            const float cn = sigm(gf) * cBr + sigm(gi) * tanh_(gg);
            cBr = cn;
            const float h = sigm(go) * tanh_(cn);
            const int j = (c << 4) + tid;
#pragma unroll
            for (int rk = 0; rk < 8; rk++) st_remote_f32(&s_hB[p ^ 1][j], rk, h);
            g_HB[(size_t)t * HN + j] = h;
            if (write_states && t == SEQN - 1) {
                out[OH + 2 * HN + j] = h;
                out[OH + 3 * HN + j] = cn;
            }
        }
        CLUSTER_SYNC_();

        if (is_ga) ga_cur = ga_next;
        p ^= 1;
    }
}

// ---------------------------------------------------------------------------
// Kernel 3: logits[t] = hB[t] @ Wfc^T + bfc
// ---------------------------------------------------------------------------
__global__ void __launch_bounds__(128) fc_kernel(const float* __restrict__ W,
                                                 const float* __restrict__ b,
                                                 float* __restrict__ out) {
    __shared__ float hs[64 * 128];
    const int tid = threadIdx.x;

    float4 w[32];
    const float4* wg = (const float4*)(W + (size_t)tid * 128);
#pragma unroll
    for (int k = 0; k < 32; k++) w[k] = wg[k];
    const float bias = b[tid];

    const int t0 = blockIdx.x * 64;
    const float4* hg = (const float4*)(g_HB + (size_t)t0 * 128);
    float4* hs4 = (float4*)hs;
#pragma unroll
    for (int i = 0; i < 16; i++) hs4[tid + (i << 7)] = hg[tid + (i << 7)];
    __syncthreads();

    for (int tt = 0; tt < 64; tt++) {
        const float4* hx = (const float4*)(hs + tt * 128);
        float a0 = 0.f, a1 = 0.f, a2 = 0.f, a3 = 0.f;
#pragma unroll
        for (int k = 0; k < 32; k++) {
            float4 h = hx[k];
            a0 = fmaf(w[k].x, h.x, a0);
            a1 = fmaf(w[k].y, h.y, a1);
            a2 = fmaf(w[k].z, h.z, a2);
            a3 = fmaf(w[k].w, h.w, a3);
        }
        out[(size_t)(t0 + tt) * 128 + tid] = (a0 + a1) + (a2 + a3) + bias;
    }
}

// ---------------------------------------------------------------------------
// launch
// inputs: 0 x, 1 hA, 2 cA, 3 hB, 4 cB, 5 WA1, 6 bA1, 7 WA2, 8 bA2,
//         9 WB1, 10 bB1, 11 WB2, 12 bB2, 13 Wfc, 14 bfc
// output: logits [SEQ*128] then hA, cA, hB, cB (if out_size covers them)
// ---------------------------------------------------------------------------
extern "C" void kernel_launch(void* const* d_in, const int* in_sizes, int n_in,
                              void* d_out, int out_size) {
    const float* x   = (const float*)d_in[0];
    const float* hA0 = (const float*)d_in[1];
    const float* cA0 = (const float*)d_in[2];
    const float* hB0 = (const float*)d_in[3];
    const float* cB0 = (const float*)d_in[4];
    const float* WA1 = (const float*)d_in[5];
    const float* bA1 = (const float*)d_in[6];
    const float* WA2 = (const float*)d_in[7];
    const float* bA2 = (const float*)d_in[8];
    const float* WB1 = (const float*)d_in[9];
    const float* bB1 = (const float*)d_in[10];
    const float* WB2 = (const float*)d_in[11];
    const float* bB2 = (const float*)d_in[12];
    const float* Wfc = (const float*)d_in[13];
    const float* bfc = (const float*)d_in[14];
    float* out = (float*)d_out;

    const int write_states = (out_size >= SEQN * HN + 4 * HN) ? 1 : 0;

    // 1. precompute input-side gates of cell A
    ga_kernel<<<dim3(SEQN / 64, 4), 128>>>(x, WA1, bA1, bA2);

    // 2. sequential recurrence (one 8-CTA cluster)
    recur_kernel<<<8, 256>>>(WA2, WB1, WB2, bB1, bB2, hA0, cA0, hB0, cB0, out,
                             write_states);

    // 3. output projection
    fc_kernel<<<SEQN / 64, 128>>>(Wfc, bfc, out);
}

// round 2
// speedup vs baseline: 1.3519x; 1.3519x over previous
#include <cuda_runtime.h>
#include <cstdint>

#define SEQN 65536
#define HN   128
#define G4   512   // 4*H

// Scratch (device globals: allocation-free per harness rules)
__device__ float g_GA[(size_t)SEQN * G4];   // precomputed x@WA1^T + bA1 + bA2
__device__ float g_HB[(size_t)SEQN * HN];   // hB per step, consumed by fc GEMM

// ---------------------------------------------------------------------------
// math helpers
// ---------------------------------------------------------------------------
__device__ __forceinline__ float sigm(float x) {
    return __fdividef(1.f, 1.f + __expf(-x));
}
__device__ __forceinline__ float tanh_(float x) {
    return 2.f * sigm(2.f * x) - 1.f;
}

__device__ __forceinline__ void st_remote_f32(float* p, int rank, float v) {
    uint32_t addr = (uint32_t)__cvta_generic_to_shared(p);
    uint32_t raddr;
    asm volatile("mapa.shared::cluster.u32 %0, %1, %2;" : "=r"(raddr) : "r"(addr), "r"(rank));
    asm volatile("st.shared::cluster.f32 [%0], %1;" :: "r"(raddr), "f"(v) : "memory");
}

#define CLUSTER_ARRIVE_() asm volatile("barrier.cluster.arrive.aligned;" ::: "memory")
#define CLUSTER_WAIT_()   asm volatile("barrier.cluster.wait.aligned;"   ::: "memory")

// ---------------------------------------------------------------------------
// Kernel 1: GA[t, 512] = x[t] @ WA1^T + bA1 + bA2
// ---------------------------------------------------------------------------
__global__ void __launch_bounds__(128) ga_kernel(const float* __restrict__ x,
                                                 const float* __restrict__ W,
                                                 const float* __restrict__ b1,
                                                 const float* __restrict__ b2) {
    __shared__ float xs[64 * 128];
    const int tid = threadIdx.x;
    const int row = (blockIdx.y << 7) + tid;

    float4 w[32];
    const float4* wg = (const float4*)(W + (size_t)row * 128);
#pragma unroll
    for (int k = 0; k < 32; k++) w[k] = wg[k];
    const float bias = b1[row] + b2[row];

    const int t0 = blockIdx.x * 64;
    const float4* xg = (const float4*)(x + (size_t)t0 * 128);
    float4* xs4 = (float4*)xs;
#pragma unroll
    for (int i = 0; i < 16; i++) xs4[tid + (i << 7)] = xg[tid + (i << 7)];
    __syncthreads();

    for (int tt = 0; tt < 64; tt++) {
        const float4* hx = (const float4*)(xs + tt * 128);
        float a0 = 0.f, a1 = 0.f, a2 = 0.f, a3 = 0.f;
#pragma unroll
        for (int k = 0; k < 32; k++) {
            float4 h = hx[k];
            a0 = fmaf(w[k].x, h.x, a0);
            a1 = fmaf(w[k].y, h.y, a1);
            a2 = fmaf(w[k].z, h.z, a2);
            a3 = fmaf(w[k].w, h.w, a3);
        }
        g_GA[(size_t)(t0 + tt) * G4 + row] = (a0 + a1) + (a2 + a3) + bias;
    }
}

// ---------------------------------------------------------------------------
// Kernel 2: pipelined recurrence. 8-CTA cluster, 384 threads each.
// Cell B runs ONE TICK BEHIND cell A, so all three matvecs at tick t depend
// only on hA(t-1) and hB(t-2) -> single merged matvec phase + ONE cluster
// sync per tick (vs two in round 1).
//
// Per CTA c (owns hidden slice j in [16c,16c+16)):
//   row slot rs = tid>>1 (0..191), half = tid&1 (64-col half)
//   mat = rs>>6: 0 -> WA2 (u), 1 -> WB1 (w), 2 -> WB2 (v); r = rs&63
//   grow = gate*128 + 16c + (r&15)
// Activations: warp0 lanes 0-15 do cell A (step t), warp1 lanes 0-15 do
// cell B (step t-1), concurrently. Double-buffered h: read buf[t&1],
// write buf[(t&1)^1].
// ---------------------------------------------------------------------------
__global__ void __cluster_dims__(8, 1, 1) __launch_bounds__(384, 1)
recur_kernel(const float* __restrict__ WA2, const float* __restrict__ WB1,
             const float* __restrict__ WB2, const float* __restrict__ bB1,
             const float* __restrict__ bB2, const float* __restrict__ hA0,
             const float* __restrict__ cA0, const float* __restrict__ hB0,
             const float* __restrict__ cB0, float* __restrict__ out,
             int write_states) {
    __shared__ float s_hA[2][HN];
    __shared__ float s_hB[2][HN];
    __shared__ float s_uA[64];   // WA2 dots (+GA)
    __shared__ float s_wB[64];   // WB1 dots
    __shared__ float s_vB[64];   // WB2 dots
    __shared__ float s_bb[64];   // bB1+bB2 for this CTA's gate rows

    const int c    = blockIdx.x;
    const int tid  = threadIdx.x;
    const int rs   = tid >> 1;      // 0..191
    const int half = tid & 1;
    const int mat  = rs >> 6;       // 0,1,2
    const int r    = rs & 63;       // 0..63
    const int grow = ((r >> 4) << 7) + (c << 4) + (r & 15);

    // ---- weights: one 64-col half-row per thread ----
    const float* Wp = (mat == 0) ? WA2 : (mat == 1) ? WB1 : WB2;
    float4 w[16];
    {
        const float4* wg = (const float4*)(Wp + (size_t)grow * 128 + half * 64);
#pragma unroll
        for (int k = 0; k < 16; k++) w[k] = wg[k];
    }

    // ---- init SMEM ----
    if (tid < 64) {
        const int gr = ((tid >> 4) << 7) + (c << 4) + (tid & 15);
        s_bb[tid] = bB1[gr] + bB2[gr];
    }
    if (tid < HN) {
        s_hA[0][tid] = hA0[tid];   // hA(-1), read at tick 0
        s_hB[1][tid] = hB0[tid];   // hB(-1), read at tick 1
        s_hB[0][tid] = 0.f;        // read (discarded) at tick 0
    }
    float cAr = 0.f, cBr = 0.f;
    if (tid < 16)                cAr = cA0[(c << 4) + tid];
    if (tid >= 32 && tid < 48)   cBr = cB0[(c << 4) + (tid - 32)];
    __syncthreads();

    // ---- GA prefetch (one lane per WA2 row) ----
    const bool is_ga = (mat == 0) && (half == 0);
    float ga_cur = 0.f, ga_next = 0.f;
    if (is_ga) ga_cur = g_GA[grow];

    const size_t OH = (size_t)SEQN * HN;   // state offset in d_out
    int p = 0;

    for (int t = 0; t <= SEQN; t++) {
        if (is_ga)
            ga_next = (t + 1 < SEQN) ? __ldg(&g_GA[(size_t)(t + 1) * G4 + grow]) : 0.f;

        // ===== merged matvec phase: u=WA2*hA(t-1), w=WB1*hA(t-1), v=WB2*hB(t-2)
        {
            const float* hsrc = (mat == 2) ? s_hB[p] : s_hA[p];
            const float4* hv4 = (const float4*)(hsrc + half * 64);
            float a0 = 0.f, a1 = 0.f, a2 = 0.f, a3 = 0.f;
#pragma unroll
            for (int k = 0; k < 16; k++) {
                float4 h = hv4[k];
                a0 = fmaf(w[k].x, h.x, a0);
                a1 = fmaf(w[k].y, h.y, a1);
                a2 = fmaf(w[k].z, h.z, a2);
                a3 = fmaf(w[k].w, h.w, a3);
            }
            float s = (a0 + a1) + (a2 + a3);
            s += __shfl_down_sync(0xffffffffu, s, 1);
            if (half == 0) {
                if (mat == 0)      s_uA[r] = s + ga_cur;
                else if (mat == 1) s_wB[r] = s;
                else               s_vB[r] = s;
            }
        }
        __syncthreads();

        // ===== cell A activation (step t), warp 0 lanes 0-15 =====
        if (tid < 16 && t < SEQN) {
            const float gi = s_uA[tid];
            const float gf = s_uA[16 + tid];
            const float gg = s_uA[32 + tid];
            const float go = s_uA[48 + tid];
            const float cn = sigm(gf) * cAr + sigm(gi) * tanh_(gg);
            cAr = cn;
            const float h = sigm(go) * tanh_(cn);
            const int j = (c << 4) + tid;
#pragma unroll
            for (int rk = 0; rk < 8; rk++) st_remote_f32(&s_hA[p ^ 1][j], rk, h);
            if (write_states && t == SEQN - 1) {
                out[OH + j]      = h;
                out[OH + HN + j] = cn;
            }
        }

        // ===== cell B activation (step t-1), warp 1 lanes 0-15 =====
        if (tid >= 32 && tid < 48 && t >= 1) {
            const int ln = tid - 32;
            const float gi = s_wB[ln]      + s_vB[ln]      + s_bb[ln];
            const float gf = s_wB[16 + ln] + s_vB[16 + ln] + s_bb[16 + ln];
            const float gg = s_wB[32 + ln] + s_vB[32 + ln] + s_bb[32 + ln];
            const float go = s_wB[48 + ln] + s_vB[48 + ln] + s_bb[48 + ln];
            const float cn = sigm(gf) * cBr + sigm(gi) * tanh_(gg);
            cBr = cn;
            const float h = sigm(go) * tanh_(cn);
            const int j = (c << 4) + ln;
#pragma unroll
            for (int rk = 0; rk < 8; rk++) st_remote_f32(&s_hB[p ^ 1][j], rk, h);
            g_HB[(size_t)(t - 1) * HN + j] = h;
            if (write_states && t == SEQN) {
                out[OH + 2 * HN + j] = h;
                out[OH + 3 * HN + j] = cn;
            }
        }

        CLUSTER_ARRIVE_();
        if (is_ga) ga_cur = ga_next;   // hidden between arrive and wait
        CLUSTER_WAIT_();
        p ^= 1;
    }
}

// ---------------------------------------------------------------------------
// Kernel 3: logits[t] = hB[t] @ Wfc^T + bfc
// ---------------------------------------------------------------------------
__global__ void __launch_bounds__(128) fc_kernel(const float* __restrict__ W,
                                                 const float* __restrict__ b,
                                                 float* __restrict__ out) {
    __shared__ float hs[64 * 128];
    const int tid = threadIdx.x;

    float4 w[32];
    const float4* wg = (const float4*)(W + (size_t)tid * 128);
#pragma unroll
    for (int k = 0; k < 32; k++) w[k] = wg[k];
    const float bias = b[tid];

    const int t0 = blockIdx.x * 64;
    const float4* hg = (const float4*)(g_HB + (size_t)t0 * 128);
    float4* hs4 = (float4*)hs;
#pragma unroll
    for (int i = 0; i < 16; i++) hs4[tid + (i << 7)] = hg[tid + (i << 7)];
    __syncthreads();

    for (int tt = 0; tt < 64; tt++) {
        const float4* hx = (const float4*)(hs + tt * 128);
        float a0 = 0.f, a1 = 0.f, a2 = 0.f, a3 = 0.f;
#pragma unroll
        for (int k = 0; k < 32; k++) {
            float4 h = hx[k];
            a0 = fmaf(w[k].x, h.x, a0);
            a1 = fmaf(w[k].y, h.y, a1);
            a2 = fmaf(w[k].z, h.z, a2);
            a3 = fmaf(w[k].w, h.w, a3);
        }
        out[(size_t)(t0 + tt) * 128 + tid] = (a0 + a1) + (a2 + a3) + bias;
    }
}

// ---------------------------------------------------------------------------
// launch
// inputs: 0 x, 1 hA, 2 cA, 3 hB, 4 cB, 5 WA1, 6 bA1, 7 WA2, 8 bA2,
//         9 WB1, 10 bB1, 11 WB2, 12 bB2, 13 Wfc, 14 bfc
// ---------------------------------------------------------------------------
extern "C" void kernel_launch(void* const* d_in, const int* in_sizes, int n_in,
                              void* d_out, int out_size) {
    const float* x   = (const float*)d_in[0];
    const float* hA0 = (const float*)d_in[1];
    const float* cA0 = (const float*)d_in[2];
    const float* hB0 = (const float*)d_in[3];
    const float* cB0 = (const float*)d_in[4];
    const float* WA1 = (const float*)d_in[5];
    const float* bA1 = (const float*)d_in[6];
    const float* WA2 = (const float*)d_in[7];
    const float* bA2 = (const float*)d_in[8];
    const float* WB1 = (const float*)d_in[9];
    const float* bB1 = (const float*)d_in[10];
    const float* WB2 = (const float*)d_in[11];
    const float* bB2 = (const float*)d_in[12];
    const float* Wfc = (const float*)d_in[13];
    const float* bfc = (const float*)d_in[14];
    float* out = (float*)d_out;

    const int write_states = (out_size >= SEQN * HN + 4 * HN) ? 1 : 0;

    ga_kernel<<<dim3(SEQN / 64, 4), 128>>>(x, WA1, bA1, bA2);
    recur_kernel<<<8, 384>>>(WA2, WB1, WB2, bB1, bB2, hA0, cA0, hB0, cB0, out,
                             write_states);
    fc_kernel<<<SEQN / 64, 128>>>(Wfc, bfc, out);
}